// round 3
// baseline (speedup 1.0000x reference)
#include <cuda_runtime.h>

// ---------------------------------------------------------------------------
// ST_Block: 66-step spatio-temporal orthogonal basis recursion + fused MLP/BN.
//
// Layout facts:
//   x        : [B=4][C=16][N=512][T=64]  -> 64 chains of 32768 floats
//   sp_matrix: [512][512], tp_matrix: [64][64]
//   out      : [B=4][64][512][64] float32
//
// Strategy: per step r, kernel A does the batched GEMM (rst = Ls@m or m@Lt)
// and fuses deterministic per-tile partial reductions of 6 dot products.
// Kernel B derives the Gram-Schmidt coefficients + analytic norm from those
// scalars, normalizes in place, and accumulates theta_r * m_r into x_st.
// ---------------------------------------------------------------------------

#define BB   4
#define CC   16
#define CH   64              // B*C chains
#define NN   512
#define TT   64
#define SLAB (NN*TT)         // 32768 floats per chain slab
#define CSZ  (CH*SLAB)       // 2097152 floats per full slab
#define NSLAB 7
#define ACCS  6              // slab index reserved for x_st accumulator
#define RTOT  66

__device__ __align__(16) float g_slab[NSLAB * CSZ];   // ~56 MB scratch
__device__ float g_part[CH][8][6];                    // per-chain per-tile partials
__device__ float g_theta[BB][RTOT];

__device__ __forceinline__ float warp_sum(float v) {
    v += __shfl_down_sync(0xffffffffu, v, 16);
    v += __shfl_down_sync(0xffffffffu, v, 8);
    v += __shfl_down_sync(0xffffffffu, v, 4);
    v += __shfl_down_sync(0xffffffffu, v, 2);
    v += __shfl_down_sync(0xffffffffu, v, 1);
    return v;
}

// ---------------------------------------------------------------------------
// theta: tiny MLP on STE. theta[b][q*11+p] = relu(h2[b,p,q])
// ---------------------------------------------------------------------------
__global__ void k_theta(const float* __restrict__ STE, const float* __restrict__ w1,
                        const float* __restrict__ b1, const float* __restrict__ w2,
                        const float* __restrict__ b2) {
    int idx = threadIdx.x;
    if (idx >= BB * RTOT) return;
    int b = idx / RTOT, rr = idx % RTOT;
    int q = rr / 11, p = rr % 11;
    float acc = b2[p];
    #pragma unroll
    for (int s = 0; s < 10; s++) {
        float h1 = b1[q];
        #pragma unroll
        for (int t = 0; t < 5; t++)
            h1 += w1[q * 5 + t] * STE[b * 50 + t * 10 + s];
        acc += w2[p * 10 + s] * h1;
    }
    g_theta[b][rr] = fmaxf(acc, 0.f);
}

// ---------------------------------------------------------------------------
// init: m00 = x / max(||x||_F, eps) into slab 0; acc = theta_0 * m00
// ---------------------------------------------------------------------------
__global__ void __launch_bounds__(256) k_init(const float* __restrict__ x) {
    int chain = blockIdx.x;
    const float* xp = x + chain * SLAB;
    float* m = g_slab + 0 * CSZ + chain * SLAB;
    float* a = g_slab + ACCS * CSZ + chain * SLAB;
    int tid = threadIdx.x;

    float s = 0.f;
    #pragma unroll
    for (int i = 0; i < 32; i++) {
        float4 v = *(const float4*)(xp + (i * 256 + tid) * 4);
        s += v.x * v.x + v.y * v.y + v.z * v.z + v.w * v.w;
    }
    __shared__ float red[8];
    __shared__ float sinv;
    float w = warp_sum(s);
    if ((tid & 31) == 0) red[tid >> 5] = w;
    __syncthreads();
    if (tid == 0) {
        float t = 0.f;
        #pragma unroll
        for (int k = 0; k < 8; k++) t += red[k];
        sinv = 1.f / fmaxf(sqrtf(t), 1e-8f);
    }
    __syncthreads();
    float inv = sinv;
    float th = g_theta[chain >> 4][0];
    #pragma unroll
    for (int i = 0; i < 32; i++) {
        int o = (i * 256 + tid) * 4;
        float4 v = *(const float4*)(xp + o);
        float4 mm, aa;
        mm.x = v.x * inv; mm.y = v.y * inv; mm.z = v.z * inv; mm.w = v.w * inv;
        aa.x = th * mm.x; aa.y = th * mm.y; aa.z = th * mm.z; aa.w = th * mm.w;
        *(float4*)(m + o) = mm;
        *(float4*)(a + o) = aa;
    }
}

// ---------------------------------------------------------------------------
// temporal GEMM: V[n][u] = sum_t X[n][t] * Lt[t][u]   (per chain, 64-row tiles)
// fused: partial dots p1..p6 over the tile -> g_part[chain][rt][*]
// ---------------------------------------------------------------------------
__global__ void __launch_bounds__(256) k_temporal(const float* __restrict__ Lt,
                                                  int inIdx, int outIdx, int secIdx) {
    int chain = blockIdx.x, rt = blockIdx.y;
    const float* X = g_slab + inIdx * CSZ + chain * SLAB + rt * 64 * TT;
    float*       V = g_slab + outIdx * CSZ + chain * SLAB + rt * 64 * TT;
    const float* S = (secIdx >= 0) ? (g_slab + secIdx * CSZ + chain * SLAB + rt * 64 * TT)
                                   : nullptr;
    __shared__ float sX[64][68];
    __shared__ float sL[64][68];
    int tid = threadIdx.x;
    #pragma unroll
    for (int i = 0; i < 4; i++) {
        int li = i * 256 + tid;
        int r = li >> 4, c4 = (li & 15) << 2;
        *(float4*)&sX[r][c4] = *(const float4*)(X + r * TT + c4);
        *(float4*)&sL[r][c4] = *(const float4*)(Lt + r * TT + c4);
    }
    __syncthreads();

    int tx = tid & 15, ty = tid >> 4;
    float acc[4][4] = {};
    #pragma unroll 16
    for (int k = 0; k < 64; k++) {
        float a[4], b[4];
        #pragma unroll
        for (int i = 0; i < 4; i++) a[i] = sX[ty + 16 * i][k];
        #pragma unroll
        for (int j = 0; j < 4; j++) b[j] = sL[k][tx + 16 * j];
        #pragma unroll
        for (int i = 0; i < 4; i++)
            #pragma unroll
            for (int j = 0; j < 4; j++) acc[i][j] += a[i] * b[j];
    }

    float p1 = 0, p2 = 0, p3 = 0, p4 = 0, p5 = 0, p6 = 0;
    #pragma unroll
    for (int i = 0; i < 4; i++) {
        int n = ty + 16 * i;
        #pragma unroll
        for (int j = 0; j < 4; j++) {
            int u = tx + 16 * j;
            float v = acc[i][j];
            V[n * TT + u] = v;
            float l  = sX[n][u];                 // last_t == matmul input, full t range in tile
            float sv = S ? S[n * TT + u] : 0.f;
            p1 += v * l;  p2 += v * sv; p3 += v * v;
            p4 += l * sv; p5 += l * l;  p6 += sv * sv;
        }
    }
    __shared__ float red[8][6];
    float r6[6] = {p1, p2, p3, p4, p5, p6};
    #pragma unroll
    for (int s = 0; s < 6; s++) {
        float w = warp_sum(r6[s]);
        if ((tid & 31) == 0) red[tid >> 5][s] = w;
    }
    __syncthreads();
    if (tid < 6) {
        float t = 0.f;
        #pragma unroll
        for (int w = 0; w < 8; w++) t += red[w][tid];
        g_part[chain][rt][tid] = t;
    }
}

// ---------------------------------------------------------------------------
// spatial GEMM: V[n][t] = sum_m Ls[n][m] * X[m][t]   (per chain, 64x64 tiles, K=512)
// ---------------------------------------------------------------------------
__global__ void __launch_bounds__(256) k_spatial(const float* __restrict__ Ls,
                                                 int inIdx, int outIdx, int secIdx) {
    int chain = blockIdx.x, nt = blockIdx.y;
    const float* Xc = g_slab + inIdx * CSZ + chain * SLAB;           // full slab
    float*       V  = g_slab + outIdx * CSZ + chain * SLAB + nt * 64 * TT;
    const float* S  = (secIdx >= 0) ? (g_slab + secIdx * CSZ + chain * SLAB + nt * 64 * TT)
                                    : nullptr;
    __shared__ float sA[64][68];
    __shared__ float sB[64][68];
    int tid = threadIdx.x;
    int tx = tid & 15, ty = tid >> 4;
    float acc[4][4] = {};

    for (int kc = 0; kc < 8; kc++) {
        #pragma unroll
        for (int i = 0; i < 4; i++) {
            int li = i * 256 + tid;
            int r = li >> 4, c4 = (li & 15) << 2;
            *(float4*)&sA[r][c4] = *(const float4*)(Ls + (nt * 64 + r) * NN + kc * 64 + c4);
            *(float4*)&sB[r][c4] = *(const float4*)(Xc + (kc * 64 + r) * TT + c4);
        }
        __syncthreads();
        #pragma unroll 16
        for (int k = 0; k < 64; k++) {
            float a[4], b[4];
            #pragma unroll
            for (int i = 0; i < 4; i++) a[i] = sA[ty + 16 * i][k];
            #pragma unroll
            for (int j = 0; j < 4; j++) b[j] = sB[k][tx + 16 * j];
            #pragma unroll
            for (int i = 0; i < 4; i++)
                #pragma unroll
                for (int j = 0; j < 4; j++) acc[i][j] += a[i] * b[j];
        }
        __syncthreads();
    }

    const float* Lc = Xc + nt * 64 * TT;   // last_s values at output positions
    float p1 = 0, p2 = 0, p3 = 0, p4 = 0, p5 = 0, p6 = 0;
    #pragma unroll
    for (int i = 0; i < 4; i++) {
        int n = ty + 16 * i;
        #pragma unroll
        for (int j = 0; j < 4; j++) {
            int t = tx + 16 * j;
            float v = acc[i][j];
            V[n * TT + t] = v;
            float l  = Lc[n * TT + t];
            float sv = S ? S[n * TT + t] : 0.f;
            p1 += v * l;  p2 += v * sv; p3 += v * v;
            p4 += l * sv; p5 += l * l;  p6 += sv * sv;
        }
    }
    __shared__ float red[8][6];
    float r6[6] = {p1, p2, p3, p4, p5, p6};
    #pragma unroll
    for (int s = 0; s < 6; s++) {
        float w = warp_sum(r6[s]);
        if ((tid & 31) == 0) red[tid >> 5][s] = w;
    }
    __syncthreads();
    if (tid < 6) {
        float t = 0.f;
        #pragma unroll
        for (int w = 0; w < 8; w++) t += red[w][tid];
        g_part[chain][nt][tid] = t;
    }
}

// ---------------------------------------------------------------------------
// update: Gram-Schmidt coeffs + analytic norm from the 6 dots; normalize V
// in place -> m_r; acc += theta_r * m_r.
//   d1 = <V,L>;  d2 = <V,S> - d1*<L,S>   (== reference's sequential <rst1,S>)
//   ||rst2||^2 = p3 - 2 d1 p1 - 2 d2 p2 + d1^2 p5 + d2^2 p6 + 2 d1 d2 p4
// ---------------------------------------------------------------------------
__global__ void __launch_bounds__(256) k_update(int vIdx, int lIdx, int sIdx, int r) {
    int chain = blockIdx.x, seg = blockIdx.y;
    float p[6] = {0, 0, 0, 0, 0, 0};
    #pragma unroll
    for (int t = 0; t < 8; t++)
        #pragma unroll
        for (int s = 0; s < 6; s++) p[s] += g_part[chain][t][s];
    float d1 = p[0];
    float d2 = p[1] - d1 * p[3];
    float n2 = p[2] - 2.f * d1 * p[0] - 2.f * d2 * p[1]
             + d1 * d1 * p[4] + d2 * d2 * p[5] + 2.f * d1 * d2 * p[3];
    float inv = 1.f / fmaxf(sqrtf(fmaxf(n2, 0.f)), 1e-8f);
    float th = g_theta[chain >> 4][r];

    int base = chain * SLAB + seg * 2048;
    float*       V = g_slab + vIdx * CSZ + base;
    const float* L = g_slab + lIdx * CSZ + base;
    const float* S = (sIdx >= 0) ? (g_slab + sIdx * CSZ + base) : nullptr;
    float*       A = g_slab + ACCS * CSZ + base;
    int tid = threadIdx.x;
    #pragma unroll
    for (int it = 0; it < 2; it++) {
        int o = (it * 256 + tid) * 4;
        float4 v = *(float4*)(V + o);
        float4 l = *(const float4*)(L + o);
        float4 s4 = S ? *(const float4*)(S + o) : make_float4(0.f, 0.f, 0.f, 0.f);
        float4 m;
        m.x = (v.x - d1 * l.x - d2 * s4.x) * inv;
        m.y = (v.y - d1 * l.y - d2 * s4.y) * inv;
        m.z = (v.z - d1 * l.z - d2 * s4.z) * inv;
        m.w = (v.w - d1 * l.w - d2 * s4.w) * inv;
        *(float4*)(V + o) = m;
        float4 a = *(float4*)(A + o);
        a.x += th * m.x; a.y += th * m.y; a.z += th * m.z; a.w += th * m.w;
        *(float4*)(A + o) = a;
    }
}

// ---------------------------------------------------------------------------
// final: out[b,o,n,t] = BN(W_mlp @ cat(x, x_st) + b)   with BN folded into W,b
// ---------------------------------------------------------------------------
__global__ void __launch_bounds__(256) k_final(const float* __restrict__ x,
                                               const float* __restrict__ wm,
                                               const float* __restrict__ bm,
                                               const float* __restrict__ gam,
                                               const float* __restrict__ bet,
                                               const float* __restrict__ mea,
                                               const float* __restrict__ var,
                                               float* __restrict__ out) {
    int b = blockIdx.x;
    int ng = blockIdx.y;                 // group of 4 n values
    __shared__ float sV[4][32][65];
    __shared__ float sW[64][32];
    __shared__ float sb2[64];
    int tid = threadIdx.x;

    for (int i = tid; i < 2048; i += 256) {
        int o = i >> 5, c = i & 31;
        float inv = gam[o] * rsqrtf(var[o] + 1e-5f);
        sW[o][c] = wm[o * 32 + c] * inv;
    }
    if (tid < 64) {
        float inv = gam[tid] * rsqrtf(var[tid] + 1e-5f);
        sb2[tid] = bm[tid] * inv + bet[tid] - mea[tid] * inv;
    }
    for (int i = tid; i < 8192; i += 256) {
        int t = i & 63, c = (i >> 6) & 31, nn = i >> 11;
        int n = ng * 4 + nn;
        float val;
        if (c < 16) val = x[((b * CC + c) * NN + n) * TT + t];
        else        val = g_slab[ACCS * CSZ + (b * CC + (c - 16)) * SLAB + n * TT + t];
        sV[nn][c][t] = val;
    }
    __syncthreads();

    int tg = tid & 63, og = tid >> 6;
    for (int oo = 0; oo < 16; oo++) {
        int o = og * 16 + oo;
        float w[32];
        #pragma unroll
        for (int c = 0; c < 32; c++) w[c] = sW[o][c];
        float bb = sb2[o];
        #pragma unroll
        for (int nn = 0; nn < 4; nn++) {
            float s = bb;
            #pragma unroll
            for (int c = 0; c < 32; c++) s += w[c] * sV[nn][c][tg];
            int n = ng * 4 + nn;
            out[((b * 64 + o) * NN + n) * TT + tg] = s;
        }
    }
}

// ---------------------------------------------------------------------------
// host: build the 131-node launch sequence (graph-capturable: launches only)
// ---------------------------------------------------------------------------
extern "C" void kernel_launch(void* const* d_in, const int* in_sizes, int n_in,
                              void* d_out, int out_size) {
    const float* x   = (const float*)d_in[0];
    const float* Ls  = (const float*)d_in[1];
    const float* Lt  = (const float*)d_in[2];
    const float* STE = (const float*)d_in[3];
    const float* w1  = (const float*)d_in[4];
    const float* b1  = (const float*)d_in[5];
    const float* w2  = (const float*)d_in[6];
    const float* b2  = (const float*)d_in[7];
    const float* wm  = (const float*)d_in[8];
    const float* bm  = (const float*)d_in[9];
    const float* gam = (const float*)d_in[10];
    const float* bet = (const float*)d_in[11];
    const float* mea = (const float*)d_in[12];
    const float* var = (const float*)d_in[13];
    float* out = (float*)d_out;
    (void)in_sizes; (void)n_in; (void)out_size;

    k_theta<<<1, 288>>>(STE, w1, b1, w2, b2);
    k_init<<<64, 256>>>(x);

    int last_s = 0, sec_s = -1, last_t = 0, sec_t = -1;
    int r = 1;
    auto pick = [&]() {
        for (int k = 0; k < 6; k++)
            if (k != last_s && k != sec_s && k != last_t && k != sec_t) return k;
        return -1;
    };
    for (int i = 0; i <= 10; i++) {
        if (i > 0) {
            int f = pick();
            k_spatial<<<dim3(64, 8), 256>>>(Ls, last_s, f, sec_s);
            k_update<<<dim3(64, 16), 256>>>(f, last_s, sec_s, r);
            sec_s = last_s; last_s = f; last_t = f; sec_t = -1; r++;
        }
        for (int j = 0; j < 5; j++) {
            int f = pick();
            k_temporal<<<dim3(64, 8), 256>>>(Lt, last_t, f, sec_t);
            k_update<<<dim3(64, 16), 256>>>(f, last_t, sec_t, r);
            sec_t = last_t; last_t = f; r++;
        }
    }
    k_final<<<dim3(4, 128), 256>>>(x, wm, bm, gam, bet, mea, var, out);
}